// round 14
// baseline (speedup 1.0000x reference)
#include <cuda_runtime.h>

// Transposed (channel-contiguous) feature scratch for the selected batch.
// 32B-aligned for 256-bit loads.
__device__ __align__(256) float g_f0[56 * 56 * 64];
__device__ __align__(256) float g_f1[28 * 28 * 128];
__device__ __align__(256) float g_f2[14 * 14 * 256];
__device__ __align__(256) float g_f3[7 * 7 * 512];

// ---------------------------------------------------------------------------
// 256-bit global access helpers (sm_100+).
// ---------------------------------------------------------------------------
__device__ __forceinline__ void stg256_cs(void* p, float4 a, float4 b) {
    asm volatile(
        "st.global.cs.v8.f32 [%0], {%1,%2,%3,%4,%5,%6,%7,%8};"
        :: "l"(p), "f"(a.x), "f"(a.y), "f"(a.z), "f"(a.w),
           "f"(b.x), "f"(b.y), "f"(b.z), "f"(b.w)
        : "memory");
}

__device__ __forceinline__ void ldg256_nc(const void* p, float4& a, float4& b) {
    asm volatile(
        "ld.global.nc.v8.f32 {%0,%1,%2,%3,%4,%5,%6,%7}, [%8];"
        : "=f"(a.x), "=f"(a.y), "=f"(a.z), "=f"(a.w),
          "=f"(b.x), "=f"(b.y), "=f"(b.z), "=f"(b.w)
        : "l"(p));
}

// ---------------------------------------------------------------------------
// Tiled transpose: src [C, SS] -> dst [SS, C], 32x32 SMEM tiles so both the
// DRAM reads and the scratch writes are fully coalesced.
// ---------------------------------------------------------------------------
template <int C, int SS>
__device__ __forceinline__ void ttile(const float* __restrict__ src,
                                      float* __restrict__ dst, int bid,
                                      float (*t)[33]) {
    constexpr int TP = (SS + 31) / 32;
    int pt = bid % TP;
    int ct = bid / TP;
    int p0 = pt * 32, c0 = ct * 32;
    int tx = threadIdx.x, ty = threadIdx.y;  // 32 x 8

#pragma unroll
    for (int j = 0; j < 32; j += 8) {
        int c = c0 + ty + j, p = p0 + tx;
        if (c < C && p < SS) t[ty + j][tx] = src[c * SS + p];
    }
    __syncthreads();
#pragma unroll
    for (int j = 0; j < 32; j += 8) {
        int p = p0 + ty + j, c = c0 + tx;
        if (c < C && p < SS) dst[p * C + c] = t[tx][ty + j];
    }
}

// Tile counts: L0: 98*2=196; L1: 25*4=100; L2: 7*8=56; L3: 2*16=32. Sum 384.
__global__ void transpose_all_kernel(const float* __restrict__ f0,
                                     const float* __restrict__ f1,
                                     const float* __restrict__ f2,
                                     const float* __restrict__ f3,
                                     const int* __restrict__ batch_p) {
    __shared__ float t[32][33];
    int b = *batch_p;
    int bid = blockIdx.x;
    if (bid < 196) {
        ttile<64, 3136>(f0 + (size_t)b * 64 * 3136, g_f0, bid, t);
    } else if (bid < 296) {
        ttile<128, 784>(f1 + (size_t)b * 128 * 784, g_f1, bid - 196, t);
    } else if (bid < 352) {
        ttile<256, 196>(f2 + (size_t)b * 256 * 196, g_f2, bid - 296, t);
    } else {
        ttile<512, 49>(f3 + (size_t)b * 512 * 49, g_f3, bid - 352, t);
    }
#if __CUDA_ARCH__ >= 900
    cudaTriggerProgrammaticLaunchCompletion();
#endif
}

// ---------------------------------------------------------------------------
// Per-level packed offset: the reference's truncated bilinear weights are
// integer; only w11=(x2-x1)*(y2-y1) can be nonzero, and it is 0 or 1.
// Returns (x1*S+y1)*C when weight==1, else -1 (row is zeros).
// ---------------------------------------------------------------------------
template <int S, int C>
__device__ __forceinline__ int level_offset(float h, float w) {
    constexpr float scale = (float)S / 224.0f;  // exact power of two
    float x = h * scale;
    float y = w * scale;
    int x1 = (int)floorf(x);
    int x2 = min((int)ceilf(x), S - 1);
    int y1 = (int)floorf(y);
    int y2 = min((int)ceilf(y), S - 1);
    return ((x2 > x1) && (y2 > y1)) ? (x1 * S + y1) * C : -1;
}

// Zero-fill one level's span of a row. 256-bit streaming stores.
template <int C, int OFF>
__device__ __forceinline__ void emit_zero(float* __restrict__ outrow, int lane) {
    float* dst = outrow + OFF;
    constexpr int N8 = C / 8;            // 8, 16, 32, 64
    constexpr int FULL = N8 / 32;        // 0, 0, 1, 2
    constexpr int REM = N8 - FULL * 32;  // 8, 16, 0, 0
    const float4 z = make_float4(0.f, 0.f, 0.f, 0.f);
#pragma unroll
    for (int i = 0; i < FULL; i++)
        stg256_cs(dst + 8 * (lane + 32 * i), z, z);
    if (REM > 0 && lane < REM)
        stg256_cs(dst + 8 * (FULL * 32 + lane), z, z);
}

// Copy one level's C channels from the transposed scratch. 256-bit ld/st.
template <int C, int OFF>
__device__ __forceinline__ void emit_copy(const float* __restrict__ fbuf,
                                          float* __restrict__ outrow,
                                          int off, int lane) {
    float* dst = outrow + OFF;
    const float* src = fbuf + off;
    constexpr int N8 = C / 8;
    constexpr int FULL = N8 / 32;
    constexpr int REM = N8 - FULL * 32;
#pragma unroll
    for (int i = 0; i < FULL; i++) {
        float4 a, b;
        ldg256_nc(src + 8 * (lane + 32 * i), a, b);
        stg256_cs(dst + 8 * (lane + 32 * i), a, b);
    }
    if (REM > 0 && lane < REM) {
        float4 a, b;
        ldg256_nc(src + 8 * (FULL * 32 + lane), a, b);
        stg256_cs(dst + 8 * (FULL * 32 + lane), a, b);
    }
}

// ---------------------------------------------------------------------------
// Main: each warp handles 8 consecutive points (measured-optimal geometry).
// Two-pass emit: zero rows/levels (~93% of the 503MB) are written BEFORE
// cudaGridDependencySynchronize() so they overlap the transpose under PDL;
// gather rows follow after the sync.
// ---------------------------------------------------------------------------
constexpr int PTS_PER_WARP = 8;

__global__ __launch_bounds__(256) void proj_kernel(const float* __restrict__ pts,
                                                   float* __restrict__ out,
                                                   int N) {
    const unsigned FULLM = 0xFFFFFFFFu;
    int warp = (blockIdx.x * blockDim.x + threadIdx.x) >> 5;
    int lane = threadIdx.x & 31;
    int base = warp * PTS_PER_WARP;
    if (base >= N) {
#if __CUDA_ARCH__ >= 900
        cudaGridDependencySynchronize();
#endif
        return;
    }

    // Coalesced load of this warp's 24 pts floats (pad-guarded).
    int nflt = min(N - base, PTS_PER_WARP) * 3;
    float v = (lane < nflt) ? __ldg(&pts[base * 3 + lane]) : 1.0f;

    // Lane l (< 8) owns point base+l.
    float px = __shfl_sync(FULLM, v, 3 * (lane & 7) + 0);
    float py = __shfl_sync(FULLM, v, 3 * (lane & 7) + 1);
    float pz = __shfl_sync(FULLM, v, 3 * (lane & 7) + 2);

    int o0 = -1, o1 = -1, o2 = -1, o3 = -1;
    if (lane < PTS_PER_WARP && base + lane < N) {
        // Match XLA rounding exactly: no FMA contraction.
        float h = __fadd_rn(__fmul_rn(248.0f, __fdiv_rn(py, pz)), 111.5f);
        float w = __fadd_rn(__fmul_rn(248.0f, __fdiv_rn(px, -pz)), 111.5f);
        h = fminf(fmaxf(h, 0.0f), 223.0f);
        w = fminf(fmaxf(w, 0.0f), 223.0f);
        o0 = level_offset<56, 64>(h, w);
        o1 = level_offset<28, 128>(h, w);
        o2 = level_offset<14, 256>(h, w);
        o3 = level_offset<7, 512>(h, w);
    }

    // Pass A: zero emits (no dependency on the transpose) — overlap the
    // transpose kernel under PDL. Offsets re-shuffled per point (no arrays:
    // keeps register count low).
#pragma unroll
    for (int i = 0; i < PTS_PER_WARP; i++) {
        int p = base + i;
        if (p >= N) break;
        float* outrow = out + (size_t)p * 960;
        if (__shfl_sync(FULLM, o0, i) < 0) emit_zero<64, 0>(outrow, lane);
        if (__shfl_sync(FULLM, o1, i) < 0) emit_zero<128, 64>(outrow, lane);
        if (__shfl_sync(FULLM, o2, i) < 0) emit_zero<256, 192>(outrow, lane);
        if (__shfl_sync(FULLM, o3, i) < 0) emit_zero<512, 448>(outrow, lane);
    }

#if __CUDA_ARCH__ >= 900
    cudaGridDependencySynchronize();
#endif

    // Pass B: gather emits (read g_f* — require transpose completion).
#pragma unroll
    for (int i = 0; i < PTS_PER_WARP; i++) {
        int p = base + i;
        if (p >= N) break;
        float* outrow = out + (size_t)p * 960;
        int s0 = __shfl_sync(FULLM, o0, i);
        int s1 = __shfl_sync(FULLM, o1, i);
        int s2 = __shfl_sync(FULLM, o2, i);
        int s3 = __shfl_sync(FULLM, o3, i);
        if (s0 >= 0) emit_copy<64, 0>(g_f0, outrow, s0, lane);
        if (s1 >= 0) emit_copy<128, 64>(g_f1, outrow, s1, lane);
        if (s2 >= 0) emit_copy<256, 192>(g_f2, outrow, s2, lane);
        if (s3 >= 0) emit_copy<512, 448>(g_f3, outrow, s3, lane);
    }
}

extern "C" void kernel_launch(void* const* d_in, const int* in_sizes, int n_in,
                              void* d_out, int out_size) {
    const float* f0 = (const float*)d_in[0];
    const float* f1 = (const float*)d_in[1];
    const float* f2 = (const float*)d_in[2];
    const float* f3 = (const float*)d_in[3];
    const float* pts = (const float*)d_in[4];
    const int* batch = (const int*)d_in[5];

    int N = in_sizes[4] / 3;  // number of points

    dim3 tblock(32, 8);
    transpose_all_kernel<<<384, tblock>>>(f0, f1, f2, f3, batch);

    int warps = (N + PTS_PER_WARP - 1) / PTS_PER_WARP;
    int blocks = (warps * 32 + 255) / 256;

    // PDL: proj's prologue + zero-fill pass overlap the transpose kernel.
    cudaLaunchConfig_t cfg = {};
    cfg.gridDim = dim3(blocks, 1, 1);
    cfg.blockDim = dim3(256, 1, 1);
    cfg.dynamicSmemBytes = 0;
    cfg.stream = 0;
    cudaLaunchAttribute attr[1];
    attr[0].id = cudaLaunchAttributeProgrammaticStreamSerialization;
    attr[0].val.programmaticStreamSerializationAllowed = 1;
    cfg.attrs = attr;
    cfg.numAttrs = 1;
    cudaError_t e = cudaLaunchKernelEx(&cfg, proj_kernel, pts, (float*)d_out, N);
    if (e != cudaSuccess) {
        proj_kernel<<<blocks, 256>>>(pts, (float*)d_out, N);
    }
}

// round 15
// speedup vs baseline: 1.0817x; 1.0817x over previous
#include <cuda_runtime.h>

// Transposed (channel-contiguous) feature scratch for the selected batch.
// 56*56*64 + 28*28*128 + 14*14*256 + 7*7*512 = 376,832 floats (~1.5 MB).
__device__ float g_f0[56 * 56 * 64];
__device__ float g_f1[28 * 28 * 128];
__device__ float g_f2[14 * 14 * 256];
__device__ float g_f3[7 * 7 * 512];

// ---------------------------------------------------------------------------
// Tiled transpose: src [C, SS] -> dst [SS, C], 32x32 SMEM tiles so both the
// DRAM reads and the scratch writes are fully coalesced.
// ---------------------------------------------------------------------------
template <int C, int SS>
__device__ __forceinline__ void ttile(const float* __restrict__ src,
                                      float* __restrict__ dst, int bid,
                                      float (*t)[33]) {
    constexpr int TP = (SS + 31) / 32;
    int pt = bid % TP;
    int ct = bid / TP;
    int p0 = pt * 32, c0 = ct * 32;
    int tx = threadIdx.x, ty = threadIdx.y;  // 32 x 8

#pragma unroll
    for (int j = 0; j < 32; j += 8) {
        int c = c0 + ty + j, p = p0 + tx;
        if (c < C && p < SS) t[ty + j][tx] = src[c * SS + p];
    }
    __syncthreads();
#pragma unroll
    for (int j = 0; j < 32; j += 8) {
        int p = p0 + ty + j, c = c0 + tx;
        if (c < C && p < SS) dst[p * C + c] = t[tx][ty + j];
    }
}

// Tile counts: L0: 98*2=196; L1: 25*4=100; L2: 7*8=56; L3: 2*16=32. Sum 384.
__global__ void transpose_all_kernel(const float* __restrict__ f0,
                                     const float* __restrict__ f1,
                                     const float* __restrict__ f2,
                                     const float* __restrict__ f3,
                                     const int* __restrict__ batch_p) {
    __shared__ float t[32][33];
    int b = *batch_p;
    int bid = blockIdx.x;
    if (bid < 196) {
        ttile<64, 3136>(f0 + (size_t)b * 64 * 3136, g_f0, bid, t);
    } else if (bid < 296) {
        ttile<128, 784>(f1 + (size_t)b * 128 * 784, g_f1, bid - 196, t);
    } else if (bid < 352) {
        ttile<256, 196>(f2 + (size_t)b * 256 * 196, g_f2, bid - 296, t);
    } else {
        ttile<512, 49>(f3 + (size_t)b * 512 * 49, g_f3, bid - 352, t);
    }
#if __CUDA_ARCH__ >= 900
    cudaTriggerProgrammaticLaunchCompletion();
#endif
}

// ---------------------------------------------------------------------------
// Per-level packed offset: the reference's truncated bilinear weights are
// integer; only w11=(x2-x1)*(y2-y1) can be nonzero, and it is 0 or 1.
// Returns (x1*S+y1)*C when weight==1, else -1 (row is zeros).
// ---------------------------------------------------------------------------
template <int S, int C>
__device__ __forceinline__ int level_offset(float h, float w) {
    constexpr float scale = (float)S / 224.0f;  // exact power of two
    float x = h * scale;
    float y = w * scale;
    int x1 = (int)floorf(x);
    int x2 = min((int)ceilf(x), S - 1);
    int y1 = (int)floorf(y);
    int y2 = min((int)ceilf(y), S - 1);
    return ((x2 > x1) && (y2 > y1)) ? (x1 * S + y1) * C : -1;
}

// Zero-fill one level's span of a row. Warp-cooperative float4 streaming.
template <int C, int OFF>
__device__ __forceinline__ void emit_zero(float* __restrict__ outrow, int lane) {
    float4* dst = (float4*)(outrow + OFF);
    constexpr int N4 = C / 4;
    constexpr int FULL = N4 / 32;
    constexpr int REM = N4 - FULL * 32;
    const float4 z = make_float4(0.f, 0.f, 0.f, 0.f);
#pragma unroll
    for (int i = 0; i < FULL; i++)
        __stcs(&dst[lane + 32 * i], z);
    if (REM > 0 && lane < REM)
        __stcs(&dst[FULL * 32 + lane], z);
}

// Copy one level's C channels from the transposed scratch. Warp-cooperative.
template <int C, int OFF>
__device__ __forceinline__ void emit_copy(const float* __restrict__ fbuf,
                                          float* __restrict__ outrow,
                                          int off, int lane) {
    float4* dst = (float4*)(outrow + OFF);
    constexpr int N4 = C / 4;
    constexpr int FULL = N4 / 32;
    constexpr int REM = N4 - FULL * 32;
    const float4* src = (const float4*)(fbuf + off);
#pragma unroll
    for (int i = 0; i < FULL; i++)
        __stcs(&dst[lane + 32 * i], __ldg(&src[lane + 32 * i]));
    if (REM > 0 && lane < REM)
        __stcs(&dst[FULL * 32 + lane], __ldg(&src[FULL * 32 + lane]));
}

// ---------------------------------------------------------------------------
// Main: each warp handles 8 consecutive points (measured-optimal geometry).
// Two-pass emit: zero rows/levels (~93% of the 503MB) are written BEFORE
// cudaGridDependencySynchronize() so they overlap the transpose under PDL;
// gather rows follow after the sync. Offsets re-shuffled inline per pass
// (no per-point register arrays: keeps regs ~40, occ up).
// ---------------------------------------------------------------------------
constexpr int PTS_PER_WARP = 8;

__global__ __launch_bounds__(256) void proj_kernel(const float* __restrict__ pts,
                                                   float* __restrict__ out,
                                                   int N) {
    const unsigned FULLM = 0xFFFFFFFFu;
    int warp = (blockIdx.x * blockDim.x + threadIdx.x) >> 5;
    int lane = threadIdx.x & 31;
    int base = warp * PTS_PER_WARP;
    if (base >= N) {
#if __CUDA_ARCH__ >= 900
        cudaGridDependencySynchronize();
#endif
        return;
    }

    // Coalesced load of this warp's 24 pts floats (pad-guarded).
    int nflt = min(N - base, PTS_PER_WARP) * 3;
    float v = (lane < nflt) ? __ldg(&pts[base * 3 + lane]) : 1.0f;

    // Lane l (< 8) owns point base+l.
    float px = __shfl_sync(FULLM, v, 3 * (lane & 7) + 0);
    float py = __shfl_sync(FULLM, v, 3 * (lane & 7) + 1);
    float pz = __shfl_sync(FULLM, v, 3 * (lane & 7) + 2);

    int o0 = -1, o1 = -1, o2 = -1, o3 = -1;
    if (lane < PTS_PER_WARP && base + lane < N) {
        // Match XLA rounding exactly: no FMA contraction.
        float h = __fadd_rn(__fmul_rn(248.0f, __fdiv_rn(py, pz)), 111.5f);
        float w = __fadd_rn(__fmul_rn(248.0f, __fdiv_rn(px, -pz)), 111.5f);
        h = fminf(fmaxf(h, 0.0f), 223.0f);
        w = fminf(fmaxf(w, 0.0f), 223.0f);
        o0 = level_offset<56, 64>(h, w);
        o1 = level_offset<28, 128>(h, w);
        o2 = level_offset<14, 256>(h, w);
        o3 = level_offset<7, 512>(h, w);
    }

    // Pass A: zero emits (no dependency on the transpose) — runs under PDL
    // overlap with the transpose kernel.
#pragma unroll
    for (int i = 0; i < PTS_PER_WARP; i++) {
        int p = base + i;
        if (p >= N) break;
        float* outrow = out + (size_t)p * 960;
        if (__shfl_sync(FULLM, o0, i) < 0) emit_zero<64, 0>(outrow, lane);
        if (__shfl_sync(FULLM, o1, i) < 0) emit_zero<128, 64>(outrow, lane);
        if (__shfl_sync(FULLM, o2, i) < 0) emit_zero<256, 192>(outrow, lane);
        if (__shfl_sync(FULLM, o3, i) < 0) emit_zero<512, 448>(outrow, lane);
    }

#if __CUDA_ARCH__ >= 900
    cudaGridDependencySynchronize();
#endif

    // Pass B: gather emits (read g_f* — require transpose completion).
#pragma unroll
    for (int i = 0; i < PTS_PER_WARP; i++) {
        int p = base + i;
        if (p >= N) break;
        float* outrow = out + (size_t)p * 960;
        int s0 = __shfl_sync(FULLM, o0, i);
        int s1 = __shfl_sync(FULLM, o1, i);
        int s2 = __shfl_sync(FULLM, o2, i);
        int s3 = __shfl_sync(FULLM, o3, i);
        if (s0 >= 0) emit_copy<64, 0>(g_f0, outrow, s0, lane);
        if (s1 >= 0) emit_copy<128, 64>(g_f1, outrow, s1, lane);
        if (s2 >= 0) emit_copy<256, 192>(g_f2, outrow, s2, lane);
        if (s3 >= 0) emit_copy<512, 448>(g_f3, outrow, s3, lane);
    }
}

extern "C" void kernel_launch(void* const* d_in, const int* in_sizes, int n_in,
                              void* d_out, int out_size) {
    const float* f0 = (const float*)d_in[0];
    const float* f1 = (const float*)d_in[1];
    const float* f2 = (const float*)d_in[2];
    const float* f3 = (const float*)d_in[3];
    const float* pts = (const float*)d_in[4];
    const int* batch = (const int*)d_in[5];

    int N = in_sizes[4] / 3;  // number of points

    dim3 tblock(32, 8);
    transpose_all_kernel<<<384, tblock>>>(f0, f1, f2, f3, batch);

    int warps = (N + PTS_PER_WARP - 1) / PTS_PER_WARP;
    int blocks = (warps * 32 + 255) / 256;

    // PDL: proj's prologue + zero-fill pass overlap the transpose kernel.
    cudaLaunchConfig_t cfg = {};
    cfg.gridDim = dim3(blocks, 1, 1);
    cfg.blockDim = dim3(256, 1, 1);
    cfg.dynamicSmemBytes = 0;
    cfg.stream = 0;
    cudaLaunchAttribute attr[1];
    attr[0].id = cudaLaunchAttributeProgrammaticStreamSerialization;
    attr[0].val.programmaticStreamSerializationAllowed = 1;
    cfg.attrs = attr;
    cfg.numAttrs = 1;
    cudaError_t e = cudaLaunchKernelEx(&cfg, proj_kernel, pts, (float*)d_out, N);
    if (e != cudaSuccess) {
        proj_kernel<<<blocks, 256>>>(pts, (float*)d_out, N);
    }
}

// round 16
// speedup vs baseline: 1.1108x; 1.0269x over previous
#include <cuda_runtime.h>

// Transposed (channel-contiguous) feature scratch for the selected batch.
// 56*56*64 + 28*28*128 + 14*14*256 + 7*7*512 = 376,832 floats (~1.5 MB).
__device__ float g_f0[56 * 56 * 64];
__device__ float g_f1[28 * 28 * 128];
__device__ float g_f2[14 * 14 * 256];
__device__ float g_f3[7 * 7 * 512];

// ---------------------------------------------------------------------------
// Tiled transpose: src [C, SS] -> dst [SS, C], 32x32 SMEM tiles so both the
// DRAM reads and the scratch writes are fully coalesced.
// ---------------------------------------------------------------------------
template <int C, int SS>
__device__ __forceinline__ void ttile(const float* __restrict__ src,
                                      float* __restrict__ dst, int bid,
                                      float (*t)[33]) {
    constexpr int TP = (SS + 31) / 32;
    int pt = bid % TP;
    int ct = bid / TP;
    int p0 = pt * 32, c0 = ct * 32;
    int tx = threadIdx.x, ty = threadIdx.y;  // 32 x 8

#pragma unroll
    for (int j = 0; j < 32; j += 8) {
        int c = c0 + ty + j, p = p0 + tx;
        if (c < C && p < SS) t[ty + j][tx] = src[c * SS + p];
    }
    __syncthreads();
#pragma unroll
    for (int j = 0; j < 32; j += 8) {
        int p = p0 + ty + j, c = c0 + tx;
        if (c < C && p < SS) dst[p * C + c] = t[tx][ty + j];
    }
}

// Tile counts: L0: 98*2=196; L1: 25*4=100; L2: 7*8=56; L3: 2*16=32. Sum 384.
__global__ void transpose_all_kernel(const float* __restrict__ f0,
                                     const float* __restrict__ f1,
                                     const float* __restrict__ f2,
                                     const float* __restrict__ f3,
                                     const int* __restrict__ batch_p) {
    __shared__ float t[32][33];
    int b = *batch_p;
    int bid = blockIdx.x;
    if (bid < 196) {
        ttile<64, 3136>(f0 + (size_t)b * 64 * 3136, g_f0, bid, t);
    } else if (bid < 296) {
        ttile<128, 784>(f1 + (size_t)b * 128 * 784, g_f1, bid - 196, t);
    } else if (bid < 352) {
        ttile<256, 196>(f2 + (size_t)b * 256 * 196, g_f2, bid - 296, t);
    } else {
        ttile<512, 49>(f3 + (size_t)b * 512 * 49, g_f3, bid - 352, t);
    }
#if __CUDA_ARCH__ >= 900
    cudaTriggerProgrammaticLaunchCompletion();
#endif
}

// ---------------------------------------------------------------------------
// Per-level packed offset: the reference's truncated bilinear weights are
// integer; only w11=(x2-x1)*(y2-y1) can be nonzero, and it is 0 or 1.
// Returns (x1*S+y1)*C when weight==1, else -1 (row is zeros).
// ---------------------------------------------------------------------------
template <int S, int C>
__device__ __forceinline__ int level_offset(float h, float w) {
    constexpr float scale = (float)S / 224.0f;  // exact power of two
    float x = h * scale;
    float y = w * scale;
    int x1 = (int)floorf(x);
    int x2 = min((int)ceilf(x), S - 1);
    int y1 = (int)floorf(y);
    int y2 = min((int)ceilf(y), S - 1);
    return ((x2 > x1) && (y2 > y1)) ? (x1 * S + y1) * C : -1;
}

// Zero-fill one level's span of a row. Warp-cooperative float4 streaming.
template <int C, int OFF>
__device__ __forceinline__ void emit_zero(float* __restrict__ outrow, int lane) {
    float4* dst = (float4*)(outrow + OFF);
    constexpr int N4 = C / 4;
    constexpr int FULL = N4 / 32;
    constexpr int REM = N4 - FULL * 32;
    const float4 z = make_float4(0.f, 0.f, 0.f, 0.f);
#pragma unroll
    for (int i = 0; i < FULL; i++)
        __stcs(&dst[lane + 32 * i], z);
    if (REM > 0 && lane < REM)
        __stcs(&dst[FULL * 32 + lane], z);
}

// Copy one level's C channels from the transposed scratch. Warp-cooperative.
template <int C, int OFF>
__device__ __forceinline__ void emit_copy(const float* __restrict__ fbuf,
                                          float* __restrict__ outrow,
                                          int off, int lane) {
    float4* dst = (float4*)(outrow + OFF);
    constexpr int N4 = C / 4;
    constexpr int FULL = N4 / 32;
    constexpr int REM = N4 - FULL * 32;
    const float4* src = (const float4*)(fbuf + off);
#pragma unroll
    for (int i = 0; i < FULL; i++)
        __stcs(&dst[lane + 32 * i], __ldg(&src[lane + 32 * i]));
    if (REM > 0 && lane < REM)
        __stcs(&dst[FULL * 32 + lane], __ldg(&src[FULL * 32 + lane]));
}

// ---------------------------------------------------------------------------
// Main: each warp handles 8 consecutive points (R7 geometry, 2048 blocks —
// the measured optimum). Two-pass emit: all zero rows/levels are written
// BEFORE cudaGridDependencySynchronize() (they don't depend on the transpose;
// ~93% of points clip, so most of the 503MB write stream overlaps the
// transpose kernel under PDL). Gather rows follow after the sync.
// Offsets are pre-gathered into register arrays so each emit pass is an
// unbroken store burst (measured faster than inline shuffles despite the
// higher register count).
// ---------------------------------------------------------------------------
constexpr int PTS_PER_WARP = 8;

__global__ __launch_bounds__(256) void proj_kernel(const float* __restrict__ pts,
                                                   float* __restrict__ out,
                                                   int N) {
    const unsigned FULLM = 0xFFFFFFFFu;
    int warp = (blockIdx.x * blockDim.x + threadIdx.x) >> 5;
    int lane = threadIdx.x & 31;
    int base = warp * PTS_PER_WARP;
    if (base >= N) {
#if __CUDA_ARCH__ >= 900
        cudaGridDependencySynchronize();
#endif
        return;
    }

    // Coalesced load of this warp's 24 pts floats (pad-guarded).
    int nflt = min(N - base, PTS_PER_WARP) * 3;
    float v = (lane < nflt) ? __ldg(&pts[base * 3 + lane]) : 1.0f;

    // Lane l (< 8) owns point base+l.
    float px = __shfl_sync(FULLM, v, 3 * (lane & 7) + 0);
    float py = __shfl_sync(FULLM, v, 3 * (lane & 7) + 1);
    float pz = __shfl_sync(FULLM, v, 3 * (lane & 7) + 2);

    int o0 = -1, o1 = -1, o2 = -1, o3 = -1;
    if (lane < PTS_PER_WARP && base + lane < N) {
        // Match XLA rounding exactly: no FMA contraction.
        float h = __fadd_rn(__fmul_rn(248.0f, __fdiv_rn(py, pz)), 111.5f);
        float w = __fadd_rn(__fmul_rn(248.0f, __fdiv_rn(px, -pz)), 111.5f);
        h = fminf(fmaxf(h, 0.0f), 223.0f);
        w = fminf(fmaxf(w, 0.0f), 223.0f);
        o0 = level_offset<56, 64>(h, w);
        o1 = level_offset<28, 128>(h, w);
        o2 = level_offset<14, 256>(h, w);
        o3 = level_offset<7, 512>(h, w);
    }

    // Gather all 8 points' offsets into per-lane arrays via shuffles.
    int q0[PTS_PER_WARP], q1[PTS_PER_WARP], q2[PTS_PER_WARP], q3[PTS_PER_WARP];
#pragma unroll
    for (int i = 0; i < PTS_PER_WARP; i++) {
        q0[i] = __shfl_sync(FULLM, o0, i);
        q1[i] = __shfl_sync(FULLM, o1, i);
        q2[i] = __shfl_sync(FULLM, o2, i);
        q3[i] = __shfl_sync(FULLM, o3, i);
    }

    // Pass A: zero emits (no dependency on the transpose) — runs under PDL
    // overlap with the transpose kernel.
#pragma unroll
    for (int i = 0; i < PTS_PER_WARP; i++) {
        int p = base + i;
        if (p >= N) break;
        float* outrow = out + (size_t)p * 960;
        if (q0[i] < 0) emit_zero<64, 0>(outrow, lane);
        if (q1[i] < 0) emit_zero<128, 64>(outrow, lane);
        if (q2[i] < 0) emit_zero<256, 192>(outrow, lane);
        if (q3[i] < 0) emit_zero<512, 448>(outrow, lane);
    }

#if __CUDA_ARCH__ >= 900
    cudaGridDependencySynchronize();
#endif

    // Pass B: gather emits (read g_f* — require transpose completion).
#pragma unroll
    for (int i = 0; i < PTS_PER_WARP; i++) {
        int p = base + i;
        if (p >= N) break;
        float* outrow = out + (size_t)p * 960;
        if (q0[i] >= 0) emit_copy<64, 0>(g_f0, outrow, q0[i], lane);
        if (q1[i] >= 0) emit_copy<128, 64>(g_f1, outrow, q1[i], lane);
        if (q2[i] >= 0) emit_copy<256, 192>(g_f2, outrow, q2[i], lane);
        if (q3[i] >= 0) emit_copy<512, 448>(g_f3, outrow, q3[i], lane);
    }
}

extern "C" void kernel_launch(void* const* d_in, const int* in_sizes, int n_in,
                              void* d_out, int out_size) {
    const float* f0 = (const float*)d_in[0];
    const float* f1 = (const float*)d_in[1];
    const float* f2 = (const float*)d_in[2];
    const float* f3 = (const float*)d_in[3];
    const float* pts = (const float*)d_in[4];
    const int* batch = (const int*)d_in[5];

    int N = in_sizes[4] / 3;  // number of points

    dim3 tblock(32, 8);
    transpose_all_kernel<<<384, tblock>>>(f0, f1, f2, f3, batch);

    int warps = (N + PTS_PER_WARP - 1) / PTS_PER_WARP;
    int blocks = (warps * 32 + 255) / 256;

    // PDL: proj's prologue + zero-fill pass overlap the transpose kernel.
    cudaLaunchConfig_t cfg = {};
    cfg.gridDim = dim3(blocks, 1, 1);
    cfg.blockDim = dim3(256, 1, 1);
    cfg.dynamicSmemBytes = 0;
    cfg.stream = 0;
    cudaLaunchAttribute attr[1];
    attr[0].id = cudaLaunchAttributeProgrammaticStreamSerialization;
    attr[0].val.programmaticStreamSerializationAllowed = 1;
    cfg.attrs = attr;
    cfg.numAttrs = 1;
    cudaError_t e = cudaLaunchKernelEx(&cfg, proj_kernel, pts, (float*)d_out, N);
    if (e != cudaSuccess) {
        proj_kernel<<<blocks, 256>>>(pts, (float*)d_out, N);
    }
}